// round 5
// baseline (speedup 1.0000x reference)
#include <cuda_runtime.h>
#include <math.h>

// Problem constants (fixed shapes)
#define BT   32768      // B*T
#define Dm   128
#define Hh   64
#define Kc   2048

#define TOK_PB   128    // tokens per block in argmin kernel
#define CODE_CH  128    // codes per smem chunk
#define STRIDE   68     // smem row stride (floats): 272B, 16B-aligned, LDS.128 conflict-free

#define N_CHUNKS (Kc / CODE_CH)   // 16
#define NT       512              // argmin threads per block

// Output layout (float32, tuple flattened in order: out, ids, commitment, codebook)
#define OUT_IDS   (BT * Hh)
#define OUT_COMM  (OUT_IDS + BT)
#define OUT_CODE  (OUT_COMM + BT)

typedef unsigned long long ull;

// Device scratch
__device__ __align__(16) float g_a[Kc];
__device__ __align__(16) float g_b[Kc];
__device__ int g_ids[BT];

// --------------------------------------------------------------------------
// Packed f32x2 FMA (sm_103a; ptxas never emits FFMA2 from C++)
// --------------------------------------------------------------------------
__device__ __forceinline__ void ffma2(ull& d, ull a, ull b) {
    asm("fma.rn.f32x2 %0, %1, %2, %0;" : "+l"(d) : "l"(a), "l"(b));
}
__device__ __forceinline__ float lo32(ull v) {
    return __int_as_float((int)(unsigned)(v & 0xffffffffull));
}
__device__ __forceinline__ float hi32(ull v) {
    return __int_as_float((int)(unsigned)(v >> 32));
}

// cp.async 16B (LDGSTS), L1-bypass
__device__ __forceinline__ void cp16(float* dst, const float* src) {
    unsigned d = (unsigned)__cvta_generic_to_shared(dst);
    asm volatile("cp.async.cg.shared.global [%0], [%1], 16;" :: "r"(d), "l"(src));
}
__device__ __forceinline__ void cp_commit() {
    asm volatile("cp.async.commit_group;");
}
__device__ __forceinline__ void cp_wait1() {
    asm volatile("cp.async.wait_group 1;" ::: "memory");
}

// --------------------------------------------------------------------------
// Kernel 1: per-code constants  a_k = 1/(2*sum exp(w_lv)),
//                               b_k = 0.5*sum(w_lv) + ||mu_e||^2 * a_k
// --------------------------------------------------------------------------
__global__ __launch_bounds__(256) void precompute_kernel(const float* __restrict__ emb) {
    int k    = blockIdx.x * 8 + (threadIdx.x >> 5);
    int lane = threadIdx.x & 31;
    if (k >= Kc) return;
    const float* row = emb + (size_t)k * Dm;
    float2 mu = *(const float2*)(row + 2 * lane);
    float2 lv = *(const float2*)(row + Hh + 2 * lane);
    float e2 = mu.x * mu.x + mu.y * mu.y;
    float se = expf(lv.x) + expf(lv.y);
    float sl = lv.x + lv.y;
    #pragma unroll
    for (int o = 16; o; o >>= 1) {
        e2 += __shfl_xor_sync(0xffffffffu, e2, o);
        se += __shfl_xor_sync(0xffffffffu, se, o);
        sl += __shfl_xor_sync(0xffffffffu, sl, o);
    }
    if (lane == 0) {
        float a = 0.5f / se;
        g_a[k] = a;
        g_b[k] = 0.5f * sl + e2 * a;
    }
}

// --------------------------------------------------------------------------
// Async prefetch of one 128-code chunk (mu rows) + a/b constants.
// 128 rows x 64 floats = 2048 16B units -> 4 per thread (512 threads).
// --------------------------------------------------------------------------
__device__ __forceinline__ void prefetch_chunk(float* Bbuf, float* ABbuf,
                                               const float* __restrict__ emb,
                                               int c0, int tid) {
    #pragma unroll
    for (int u = 0; u < 4; u++) {
        int idx = tid + NT * u;
        int row = idx >> 4, col = idx & 15;
        cp16(Bbuf + row * STRIDE + col * 4,
             emb + (size_t)(c0 + row) * Dm + col * 4);
    }
    if (tid < 32)       cp16(ABbuf + tid * 4,               g_a + c0 + tid * 4);
    else if (tid < 64)  cp16(ABbuf + 128 + (tid - 32) * 4,  g_b + c0 + (tid - 32) * 4);
}

// --------------------------------------------------------------------------
// Kernel 2: argmin over codes.
// Block: 512 threads. tx = tid&31 (codes: tx + 32j, j<4), ty = tid>>5 = warp
// (tokens: ty + 16i, i<8). av loads are warp-uniform broadcasts; bv LDS.128
// is phase-conflict-free with STRIDE 68. k unrolled by 4 (ulonglong2 pairs).
// Code tile (128 x 64) double-buffered via cp.async ping-pong.
// --------------------------------------------------------------------------
__global__ __launch_bounds__(NT, 1) void argmin_kernel(const float* __restrict__ x,
                                                       const float* __restrict__ emb) {
    extern __shared__ float sm[];
    float* A_s  = sm;                              // 128*68
    float* B_s  = sm + TOK_PB * STRIDE;            // 2 x 128*68
    float* AB_s = B_s + 2 * CODE_CH * STRIDE;      // 2 x 256  (a[128] then b[128])
    float* Ci_s = AB_s + 512;                      // 128

    int tid  = threadIdx.x;
    int warp = tid >> 5, lane = tid & 31;
    int tok0 = blockIdx.x * TOK_PB;

    // Kick off chunk-0 prefetch immediately; overlap with A-tile load.
    prefetch_chunk(B_s, AB_s, emb, 0, tid);
    cp_commit();

    // ---- Load token tile: mu -> A_s, C_i = ||mu||^2 + sum exp(logvar) ----
    #pragma unroll
    for (int i = 0; i < 8; i++) {
        int t = warp * 8 + i;
        float4 v = *(const float4*)(x + (size_t)(tok0 + t) * Dm + lane * 4);
        float p;
        if (lane < 16) {
            *(float4*)&A_s[t * STRIDE + lane * 4] = v;
            p = v.x * v.x + v.y * v.y + v.z * v.z + v.w * v.w;
        } else {
            p = expf(v.x) + expf(v.y) + expf(v.z) + expf(v.w);
        }
        #pragma unroll
        for (int o = 16; o; o >>= 1) p += __shfl_xor_sync(0xffffffffu, p, o);
        if (lane == 0) Ci_s[t] = p;
    }

    int ty = warp;           // token group (warp-uniform)
    int tx = lane;           // code column
    const float* Arow = A_s + ty * STRIDE;

    float best[8];
    int   bidx[8];
    #pragma unroll
    for (int i = 0; i < 8; i++) { best[i] = 3.4e38f; bidx[i] = 0; }

    __syncthreads();   // A_s / Ci_s ready

    for (int ch = 0; ch < N_CHUNKS; ch++) {
        int buf = ch & 1;
        float* Bb  = B_s + buf * CODE_CH * STRIDE;
        float* ABb = AB_s + buf * 256;

        if (ch < N_CHUNKS - 1)
            prefetch_chunk(B_s + (buf ^ 1) * CODE_CH * STRIDE,
                           AB_s + (buf ^ 1) * 256, emb, (ch + 1) * CODE_CH, tid);
        cp_commit();
        cp_wait1();        // chunk ch data landed (per-thread)
        __syncthreads();   // ... and visible to all threads

        ull acc[8][4];
        #pragma unroll
        for (int i = 0; i < 8; i++)
            #pragma unroll
            for (int j = 0; j < 4; j++) acc[i][j] = 0ull;

        const float* Brow = Bb + tx * STRIDE;

        #pragma unroll 1
        for (int k = 0; k < Hh; k += 4) {
            ulonglong2 bv[4];
            #pragma unroll
            for (int j = 0; j < 4; j++)
                bv[j] = *(const ulonglong2*)(Brow + j * 32 * STRIDE + k);
            // i-loop in halves: caps live av registers at 4x ulonglong2
            #pragma unroll
            for (int half = 0; half < 2; half++) {
                ulonglong2 av[4];
                #pragma unroll
                for (int i = 0; i < 4; i++)
                    av[i] = *(const ulonglong2*)(Arow + (half * 4 + i) * 16 * STRIDE + k);
                #pragma unroll
                for (int i = 0; i < 4; i++)
                    #pragma unroll
                    for (int j = 0; j < 4; j++) {
                        ffma2(acc[half * 4 + i][j], av[i].x, bv[j].x);
                        ffma2(acc[half * 4 + i][j], av[i].y, bv[j].y);
                    }
            }
        }

        // Fold scores into running argmin (ascending code order + strict <
        // matches jnp.argmin first-min tie-break).
        int cbase = ch * CODE_CH + tx;
        #pragma unroll
        for (int j = 0; j < 4; j++) {
            float aa = ABb[tx + 32 * j];
            float bb = ABb[128 + tx + 32 * j];
            int   c  = cbase + 32 * j;
            #pragma unroll
            for (int i = 0; i < 8; i++) {
                float dot = lo32(acc[i][j]) + hi32(acc[i][j]);
                float s = fmaf(aa, fmaf(-2.0f, dot, Ci_s[ty + 16 * i]), bb);
                if (s < best[i]) { best[i] = s; bidx[i] = c; }
            }
        }
        __syncthreads();   // done reading Bb/ABb; next iter may overwrite
    }

    // Reduce over the 32 lanes of the warp (all share token ty + 16*i).
    #pragma unroll
    for (int i = 0; i < 8; i++) {
        float s = best[i];
        int   c = bidx[i];
        #pragma unroll
        for (int o = 1; o < 32; o <<= 1) {
            float s2 = __shfl_xor_sync(0xffffffffu, s, o);
            int   c2 = __shfl_xor_sync(0xffffffffu, c, o);
            if (s2 < s || (s2 == s && c2 < c)) { s = s2; c = c2; }
        }
        if (lane == 0) g_ids[tok0 + ty + 16 * i] = c;
    }
}

// --------------------------------------------------------------------------
// Kernel 3: epilogue. One warp per token.
// --------------------------------------------------------------------------
__global__ __launch_bounds__(256) void epilogue_kernel(const float* __restrict__ x,
                                                       const float* __restrict__ emb,
                                                       const float* __restrict__ z,
                                                       float* __restrict__ out) {
    int warp = threadIdx.x >> 5, lane = threadIdx.x & 31;
    int token = blockIdx.x * 8 + warp;
    int id = g_ids[token];
    const float* w  = emb + (size_t)id * Dm;
    const float* xr = x + (size_t)token * Dm;

    float4 wv = *(const float4*)(w  + lane * 4);
    float4 xv = *(const float4*)(xr + lane * 4);
    float d0 = wv.x - xv.x, d1 = wv.y - xv.y, d2 = wv.z - xv.z, d3 = wv.w - xv.w;
    float p = d0 * d0 + d1 * d1 + d2 * d2 + d3 * d3;
    #pragma unroll
    for (int o = 16; o; o >>= 1) p += __shfl_xor_sync(0xffffffffu, p, o);

    #pragma unroll
    for (int r = 0; r < 2; r++) {
        int h = lane + 32 * r;
        float mu = w[h];
        float lv = w[Hh + h];
        float zz = z[(size_t)token * Hh + h];
        out[(size_t)token * Hh + h] = fmaf(expf(0.5f * lv), zz, mu);
    }
    if (lane == 0) {
        float m = p * (1.0f / (float)Dm);
        out[OUT_IDS  + token] = (float)id;
        out[OUT_COMM + token] = m;
        out[OUT_CODE + token] = m;
    }
}

// --------------------------------------------------------------------------
extern "C" void kernel_launch(void* const* d_in, const int* in_sizes, int n_in,
                              void* d_out, int out_size) {
    const float *x = nullptr, *emb = nullptr, *z = nullptr;
    for (int i = 0; i < n_in; i++) {
        if (in_sizes[i] == BT * Dm)      x   = (const float*)d_in[i];
        else if (in_sizes[i] == Kc * Dm) emb = (const float*)d_in[i];
        else if (in_sizes[i] == BT * Hh) z   = (const float*)d_in[i];
    }
    float* out = (float*)d_out;

    const int SMEM_BYTES = (TOK_PB * STRIDE + 2 * CODE_CH * STRIDE + 512 + 128) * 4;
    cudaFuncSetAttribute(argmin_kernel,
                         cudaFuncAttributeMaxDynamicSharedMemorySize, SMEM_BYTES);

    precompute_kernel<<<Kc / 8, 256>>>(emb);
    argmin_kernel<<<BT / TOK_PB, NT, SMEM_BYTES>>>(x, emb);
    epilogue_kernel<<<BT / 8, 256>>>(x, emb, z, out);
    (void)out_size;
}

// round 8
// speedup vs baseline: 1.8721x; 1.8721x over previous
#include <cuda_runtime.h>
#include <cuda_fp16.h>
#include <math.h>
#include <stdint.h>

// Problem constants (fixed shapes)
#define BT   32768      // B*T
#define Dm   128
#define Hh   64
#define Kc   2048

#define TOK_PB   128    // tokens per argmin CTA
#define CHUNK    64     // codes per B chunk
#define NCHK     (Kc / CHUNK)    // 32
#define KPAD     256    // concatenated K (4 segments of 64)
#define KIT      (KPAD / 16)     // 16 k-iterations
#define SA       264    // smem row stride in halves (528B, ldmatrix conflict-free)

// Output layout (float32 tuple: out, ids, commitment, codebook)
#define OUT_IDS   (BT * Hh)
#define OUT_COMM  (OUT_IDS + BT)
#define OUT_CODE  (OUT_COMM + BT)

// Device scratch
__device__ __align__(16) float g_a[Kc];
__device__ __align__(16) float g_b[Kc];
__device__ int g_ids[BT];
// B_cat: per code 256 fp16 = segments [wh, wh, wm, wm] of (16*w_d)
__device__ __align__(16) __half g_bcat[Kc * KPAD];

// --------------------------------------------------------------------------
// PTX helpers — all plain sm_80-era features (legal on target compute_103)
// --------------------------------------------------------------------------
__device__ __forceinline__ uint32_t smem_u32(const void* p) {
    uint32_t a;
    asm("{ .reg .u64 t; cvta.to.shared.u64 t, %1; cvt.u32.u64 %0, t; }"
        : "=r"(a) : "l"(p));
    return a;
}
__device__ __forceinline__ void cp16s(uint32_t dst, const void* src) {
    asm volatile("cp.async.cg.shared.global [%0], [%1], 16;" :: "r"(dst), "l"(src));
}
__device__ __forceinline__ void cp_commit() { asm volatile("cp.async.commit_group;"); }
__device__ __forceinline__ void cp_wait1()  { asm volatile("cp.async.wait_group 1;" ::: "memory"); }
__device__ __forceinline__ void cp_wait0()  { asm volatile("cp.async.wait_group 0;" ::: "memory"); }

__device__ __forceinline__ void ldsm4(uint32_t* r, uint32_t addr) {
    asm volatile("ldmatrix.sync.aligned.m8n8.x4.shared.b16 {%0,%1,%2,%3}, [%4];"
        : "=r"(r[0]), "=r"(r[1]), "=r"(r[2]), "=r"(r[3]) : "r"(addr));
}
__device__ __forceinline__ void mma16816(float* d, const uint32_t* a, const uint32_t* b) {
    asm volatile(
        "mma.sync.aligned.m16n8k16.row.col.f32.f16.f16.f32 "
        "{%0,%1,%2,%3}, {%4,%5,%6,%7}, {%8,%9}, {%0,%1,%2,%3};"
        : "+f"(d[0]), "+f"(d[1]), "+f"(d[2]), "+f"(d[3])
        : "r"(a[0]), "r"(a[1]), "r"(a[2]), "r"(a[3]), "r"(b[0]), "r"(b[1]));
}

// --------------------------------------------------------------------------
// Kernel 1a: per-code constants  a_k = 1/(2*sum exp(w_lv)),
//            b_k = 0.5*sum(w_lv) + ||mu_e||^2 * a_k
// --------------------------------------------------------------------------
__global__ __launch_bounds__(256) void precompute_kernel(const float* __restrict__ emb) {
    int k    = blockIdx.x * 8 + (threadIdx.x >> 5);
    int lane = threadIdx.x & 31;
    if (k >= Kc) return;
    const float* row = emb + (size_t)k * Dm;
    float2 mu = *(const float2*)(row + 2 * lane);
    float2 lv = *(const float2*)(row + Hh + 2 * lane);
    float e2 = mu.x * mu.x + mu.y * mu.y;
    float se = expf(lv.x) + expf(lv.y);
    float sl = lv.x + lv.y;
    #pragma unroll
    for (int o = 16; o; o >>= 1) {
        e2 += __shfl_xor_sync(0xffffffffu, e2, o);
        se += __shfl_xor_sync(0xffffffffu, se, o);
        sl += __shfl_xor_sync(0xffffffffu, sl, o);
    }
    if (lane == 0) {
        float a = 0.5f / se;
        g_a[k] = a;
        g_b[k] = 0.5f * sl + e2 * a;
    }
}

// --------------------------------------------------------------------------
// Kernel 1b: build B_cat fp16 limbs of 16*w. One 64-thread block per code.
// --------------------------------------------------------------------------
__global__ __launch_bounds__(64) void bcat_kernel(const float* __restrict__ emb) {
    int k = blockIdx.x;
    int d = threadIdx.x;                 // 0..63
    float s = 16.0f * emb[(size_t)k * Dm + d];
    __half h = __float2half_rn(s);
    __half m = __float2half_rn(s - __half2float(h));
    __half* o = g_bcat + (size_t)k * KPAD;
    o[0 * Hh + d] = h;
    o[1 * Hh + d] = h;
    o[2 * Hh + d] = m;
    o[3 * Hh + d] = m;
}

// --------------------------------------------------------------------------
// Kernel 2: HMMA argmin. 256 threads, 128 tokens/CTA, grid 256.
// A (128 x 256 fp16, stride 264) in smem; B chunks (64 codes x 256)
// double-buffered via cp.async. Warp grid 4x2: wm = token group of 32,
// wn = code half of 32. Per warp m32 x n32 per chunk via m16n8k16.
// dot256 = 256 * dot;  score = a*(Ci - dot256/128) + b.
// --------------------------------------------------------------------------
__device__ __forceinline__ void prefetch_b(uint32_t bbase, int c0, int tid) {
    #pragma unroll
    for (int q = 0; q < 8; q++) {
        int idx = tid + 256 * q;          // 0..2047 16B units
        int row = idx >> 5, u = idx & 31;
        cp16s(bbase + row * (SA * 2) + u * 16,
              g_bcat + ((size_t)(c0 + row) * KPAD + u * 8));
    }
}

__global__ __launch_bounds__(256, 1) void argmin_mma_kernel(const float* __restrict__ x) {
    extern __shared__ __half sm[];
    // layout (halves): A[128*264] | B0[64*264] | B1[64*264] | ab(4096 f32) | Ci(128 f32)
    __half* A_s = sm;
    float*  ab  = (float*)(sm + (TOK_PB + 2 * CHUNK) * SA);
    float*  Ci_s = ab + 2 * Kc;

    __shared__ float sred_s[2][TOK_PB];
    __shared__ int   sred_i[2][TOK_PB];

    int tid  = threadIdx.x;
    int warp = tid >> 5, lane = tid & 31;
    int tok0 = blockIdx.x * TOK_PB;
    int wm = warp & 3, wn = warp >> 2;

    uint32_t smbase = smem_u32(sm);
    uint32_t b0a = smbase + TOK_PB * SA * 2;
    uint32_t b1a = b0a + CHUNK * SA * 2;

    // chunk-0 B prefetch first (overlaps A build)
    prefetch_b(b0a, 0, tid);
    cp_commit();

    // a/b tables -> smem (4096 floats, 4 x float4 per thread)
    {
        const float4* ga4 = (const float4*)g_a;
        const float4* gb4 = (const float4*)g_b;
        #pragma unroll
        for (int q = 0; q < 2; q++) ((float4*)ab)[tid + 256 * q]        = ga4[tid + 256 * q];
        #pragma unroll
        for (int q = 0; q < 2; q++) ((float4*)(ab + Kc))[tid + 256 * q] = gb4[tid + 256 * q];
    }

    // A build: one token per thread (tid<128): limbs of 16*x + Ci
    if (tid < TOK_PB) {
        const float* xr = x + (size_t)(tok0 + tid) * Dm;
        float Ci = 0.0f;
        __half2* arow = (__half2*)(A_s + tid * SA);
        #pragma unroll
        for (int d = 0; d < Hh; d += 2) {
            float2 v = *(const float2*)(xr + d);
            Ci += v.x * v.x + v.y * v.y;
            float s0 = 16.0f * v.x, s1 = 16.0f * v.y;
            __half h0 = __float2half_rn(s0), h1 = __float2half_rn(s1);
            __half m0 = __float2half_rn(s0 - __half2float(h0));
            __half m1 = __float2half_rn(s1 - __half2float(h1));
            __half2 hh = __halves2half2(h0, h1);
            __half2 mm = __halves2half2(m0, m1);
            arow[(0 * Hh + d) >> 1] = hh;
            arow[(1 * Hh + d) >> 1] = mm;
            arow[(2 * Hh + d) >> 1] = hh;
            arow[(3 * Hh + d) >> 1] = mm;
        }
        #pragma unroll
        for (int d = 0; d < Hh; d += 4) {
            float4 v = *(const float4*)(xr + Hh + d);
            Ci += expf(v.x) + expf(v.y) + expf(v.z) + expf(v.w);
        }
        Ci_s[tid] = Ci;
    }
    __syncthreads();   // A_s, ab, Ci_s ready

    // ldmatrix per-lane offsets
    // A x4: rows m_base + (lane&15), koff = (lane>>4)*8 halves
    uint32_t a_off0 = smbase + ((wm * 32 + (lane & 15)) * SA + (lane >> 4) * 8) * 2;
    uint32_t a_off1 = a_off0 + 16 * SA * 2;
    // B x4 (2 n8-tiles): rows n_base + (lane&7) + ((lane>>4)<<3), koff = ((lane>>3)&1)*8
    uint32_t b_off = ((wn * 32 + (lane & 7) + ((lane >> 4) << 3)) * SA
                    + ((lane >> 3) & 1) * 8) * 2;

    int g  = lane >> 2, tc = lane & 3;
    float Ci_r[4];
    #pragma unroll
    for (int s = 0; s < 4; s++)
        Ci_r[s] = Ci_s[wm * 32 + (s >> 1) * 16 + (s & 1) * 8 + g];

    float best[4];
    int   bidx[4];
    #pragma unroll
    for (int s = 0; s < 4; s++) { best[s] = 3.4e38f; bidx[s] = 0; }

    for (int ch = 0; ch < NCHK; ch++) {
        uint32_t bb = (ch & 1) ? b1a : b0a;

        if (ch < NCHK - 1) {
            prefetch_b((ch & 1) ? b0a : b1a, (ch + 1) * CHUNK, tid);
            cp_commit();
            cp_wait1();           // chunk ch landed
        } else {
            cp_wait0();
        }
        __syncthreads();          // visible block-wide

        float acc[2][4][4];
        #pragma unroll
        for (int mt = 0; mt < 2; mt++)
            #pragma unroll
            for (int nt = 0; nt < 4; nt++)
                #pragma unroll
                for (int c = 0; c < 4; c++) acc[mt][nt][c] = 0.0f;

        #pragma unroll 1
        for (int k = 0; k < KIT; k++) {
            uint32_t kb = (uint32_t)k * 32;       // 16 halves
            uint32_t af0[4], af1[4], bf0[4], bf1[4];
            ldsm4(af0, a_off0 + kb);
            ldsm4(af1, a_off1 + kb);
            ldsm4(bf0, bb + b_off + kb);
            ldsm4(bf1, bb + b_off + 16 * SA * 2 + kb);
            mma16816(acc[0][0], af0, bf0 + 0);
            mma16816(acc[0][1], af0, bf0 + 2);
            mma16816(acc[0][2], af0, bf1 + 0);
            mma16816(acc[0][3], af0, bf1 + 2);
            mma16816(acc[1][0], af1, bf0 + 0);
            mma16816(acc[1][1], af1, bf0 + 2);
            mma16816(acc[1][2], af1, bf1 + 0);
            mma16816(acc[1][3], af1, bf1 + 2);
        }

        // fold scores (codes ascending; strict < keeps first min like jnp.argmin)
        int cb = ch * CHUNK + wn * 32 + 2 * tc;
        #pragma unroll
        for (int nt = 0; nt < 4; nt++) {
            int c0 = cb + nt * 8;
            float a0 = ab[c0],     b0v = ab[Kc + c0];
            float a1 = ab[c0 + 1], b1v = ab[Kc + c0 + 1];
            #pragma unroll
            for (int mt = 0; mt < 2; mt++)
                #pragma unroll
                for (int c = 0; c < 4; c++) {
                    int slot = mt * 2 + (c >> 1);
                    float aa = (c & 1) ? a1 : a0;
                    float bbv = (c & 1) ? b1v : b0v;
                    float s = fmaf(aa, fmaf(-0.0078125f, acc[mt][nt][c], Ci_r[slot]), bbv);
                    int code = c0 + (c & 1);
                    if (s < best[slot]) { best[slot] = s; bidx[slot] = code; }
                }
        }
        __syncthreads();          // all reads of bb done before it is overwritten
    }

    // reduce across the 4 tc-lanes sharing each token row
    #pragma unroll
    for (int s = 0; s < 4; s++) {
        float v = best[s];
        int   c = bidx[s];
        #pragma unroll
        for (int o = 1; o < 4; o <<= 1) {
            float v2 = __shfl_xor_sync(0xffffffffu, v, o);
            int   c2 = __shfl_xor_sync(0xffffffffu, c, o);
            if (v2 < v || (v2 == v && c2 < c)) { v = v2; c = c2; }
        }
        if (tc == 0) {
            int row = wm * 32 + (s >> 1) * 16 + (s & 1) * 8 + g;
            sred_s[wn][row] = v;
            sred_i[wn][row] = c;
        }
    }
    __syncthreads();

    if (tid < TOK_PB) {
        float s0 = sred_s[0][tid], s1 = sred_s[1][tid];
        int   c0 = sred_i[0][tid], c1 = sred_i[1][tid];
        g_ids[tok0 + tid] = (s1 < s0 || (s1 == s0 && c1 < c0)) ? c1 : c0;
    }
}

// --------------------------------------------------------------------------
// Kernel 3: epilogue. One warp per token.
// --------------------------------------------------------------------------
__global__ __launch_bounds__(256) void epilogue_kernel(const float* __restrict__ x,
                                                       const float* __restrict__ emb,
                                                       const float* __restrict__ z,
                                                       float* __restrict__ out) {
    int warp = threadIdx.x >> 5, lane = threadIdx.x & 31;
    int token = blockIdx.x * 8 + warp;
    int id = g_ids[token];
    const float* w  = emb + (size_t)id * Dm;
    const float* xr = x + (size_t)token * Dm;

    float4 wv = *(const float4*)(w  + lane * 4);
    float4 xv = *(const float4*)(xr + lane * 4);
    float d0 = wv.x - xv.x, d1 = wv.y - xv.y, d2 = wv.z - xv.z, d3 = wv.w - xv.w;
    float p = d0 * d0 + d1 * d1 + d2 * d2 + d3 * d3;
    #pragma unroll
    for (int o = 16; o; o >>= 1) p += __shfl_xor_sync(0xffffffffu, p, o);

    #pragma unroll
    for (int r = 0; r < 2; r++) {
        int h = lane + 32 * r;
        float mu = w[h];
        float lv = w[Hh + h];
        float zz = z[(size_t)token * Hh + h];
        out[(size_t)token * Hh + h] = fmaf(expf(0.5f * lv), zz, mu);
    }
    if (lane == 0) {
        float m = p * (1.0f / (float)Dm);
        out[OUT_IDS  + token] = (float)id;
        out[OUT_COMM + token] = m;
        out[OUT_CODE + token] = m;
    }
}

// --------------------------------------------------------------------------
extern "C" void kernel_launch(void* const* d_in, const int* in_sizes, int n_in,
                              void* d_out, int out_size) {
    const float *x = nullptr, *emb = nullptr, *z = nullptr;
    for (int i = 0; i < n_in; i++) {
        if (in_sizes[i] == BT * Dm)      x   = (const float*)d_in[i];
        else if (in_sizes[i] == Kc * Dm) emb = (const float*)d_in[i];
        else if (in_sizes[i] == BT * Hh) z   = (const float*)d_in[i];
    }
    float* out = (float*)d_out;

    // dyn smem: (128 + 2*64) rows * 264 halves + ab tables + Ci
    const int SMEM_BYTES = (TOK_PB + 2 * CHUNK) * SA * 2 + 2 * Kc * 4 + TOK_PB * 4;
    cudaFuncSetAttribute(argmin_mma_kernel,
                         cudaFuncAttributeMaxDynamicSharedMemorySize, SMEM_BYTES);

    precompute_kernel<<<Kc / 8, 256>>>(emb);
    bcat_kernel<<<Kc, 64>>>(emb);
    argmin_mma_kernel<<<BT / TOK_PB, 256, SMEM_BYTES>>>(x);
    epilogue_kernel<<<BT / 8, 256>>>(x, emb, z, out);
    (void)out_size;
}

// round 10
// speedup vs baseline: 2.2642x; 1.2095x over previous
#include <cuda_runtime.h>
#include <cuda_fp16.h>
#include <math.h>
#include <stdint.h>

// Problem constants (fixed shapes)
#define BT   32768      // B*T
#define Dm   128
#define Hh   64
#define Kc   2048

#define TOK_PB   128    // tokens per argmin CTA
#define CHUNK    64     // codes per B chunk
#define NCHK     (Kc / CHUNK)    // 32
#define KPAD     192    // concatenated K (3 segments of 64: hh, mh, hm)
#define KIT      (KPAD / 16)     // 12 k-iterations
#define SA       200    // smem row stride in halves (400B; 400%128=16 -> ldsm conflict-free)

// Output layout (float32 tuple: out, ids, commitment, codebook)
#define OUT_IDS   (BT * Hh)
#define OUT_COMM  (OUT_IDS + BT)
#define OUT_CODE  (OUT_COMM + BT)

// Device scratch
__device__ __align__(16) float g_a[Kc];
__device__ __align__(16) float g_b[Kc];
// B_cat: per code 192 fp16 = segments [wh, wh, wm] of (16*w_d)
__device__ __align__(16) __half g_bcat[Kc * KPAD];

// --------------------------------------------------------------------------
// PTX helpers — all plain sm_80-era features (legal on target compute_103)
// --------------------------------------------------------------------------
__device__ __forceinline__ uint32_t smem_u32(const void* p) {
    uint32_t a;
    asm("{ .reg .u64 t; cvta.to.shared.u64 t, %1; cvt.u32.u64 %0, t; }"
        : "=r"(a) : "l"(p));
    return a;
}
__device__ __forceinline__ void cp16s(uint32_t dst, const void* src) {
    asm volatile("cp.async.cg.shared.global [%0], [%1], 16;" :: "r"(dst), "l"(src));
}
__device__ __forceinline__ void cp_commit() { asm volatile("cp.async.commit_group;"); }
__device__ __forceinline__ void cp_wait1()  { asm volatile("cp.async.wait_group 1;" ::: "memory"); }
__device__ __forceinline__ void cp_wait0()  { asm volatile("cp.async.wait_group 0;" ::: "memory"); }

__device__ __forceinline__ void ldsm4(uint32_t* r, uint32_t addr) {
    asm volatile("ldmatrix.sync.aligned.m8n8.x4.shared.b16 {%0,%1,%2,%3}, [%4];"
        : "=r"(r[0]), "=r"(r[1]), "=r"(r[2]), "=r"(r[3]) : "r"(addr));
}
__device__ __forceinline__ void mma16816(float* d, const uint32_t* a, const uint32_t* b) {
    asm volatile(
        "mma.sync.aligned.m16n8k16.row.col.f32.f16.f16.f32 "
        "{%0,%1,%2,%3}, {%4,%5,%6,%7}, {%8,%9}, {%0,%1,%2,%3};"
        : "+f"(d[0]), "+f"(d[1]), "+f"(d[2]), "+f"(d[3])
        : "r"(a[0]), "r"(a[1]), "r"(a[2]), "r"(a[3]), "r"(b[0]), "r"(b[1]));
}

// --------------------------------------------------------------------------
// Kernel 1a: per-code constants  a_k = 1/(2*sum exp(w_lv)),
//            b_k = 0.5*sum(w_lv) + ||mu_e||^2 * a_k
// --------------------------------------------------------------------------
__global__ __launch_bounds__(256) void precompute_kernel(const float* __restrict__ emb) {
    int k    = blockIdx.x * 8 + (threadIdx.x >> 5);
    int lane = threadIdx.x & 31;
    if (k >= Kc) return;
    const float* row = emb + (size_t)k * Dm;
    float2 mu = *(const float2*)(row + 2 * lane);
    float2 lv = *(const float2*)(row + Hh + 2 * lane);
    float e2 = mu.x * mu.x + mu.y * mu.y;
    float se = expf(lv.x) + expf(lv.y);
    float sl = lv.x + lv.y;
    #pragma unroll
    for (int o = 16; o; o >>= 1) {
        e2 += __shfl_xor_sync(0xffffffffu, e2, o);
        se += __shfl_xor_sync(0xffffffffu, se, o);
        sl += __shfl_xor_sync(0xffffffffu, sl, o);
    }
    if (lane == 0) {
        float a = 0.5f / se;
        g_a[k] = a;
        g_b[k] = 0.5f * sl + e2 * a;
    }
}

// --------------------------------------------------------------------------
// Kernel 1b: build B_cat fp16 limbs of 16*w. 4 codes per 256-thread block.
// --------------------------------------------------------------------------
__global__ __launch_bounds__(256) void bcat_kernel(const float* __restrict__ emb) {
    int k = blockIdx.x * 4 + (threadIdx.x >> 6);
    int d = threadIdx.x & 63;
    float s = 16.0f * emb[(size_t)k * Dm + d];
    __half h = __float2half_rn(s);
    __half m = __float2half_rn(s - __half2float(h));
    __half* o = g_bcat + (size_t)k * KPAD;
    o[0 * Hh + d] = h;
    o[1 * Hh + d] = h;
    o[2 * Hh + d] = m;
}

// --------------------------------------------------------------------------
// Kernel 2: HMMA argmin + fused epilogue. 256 threads, 128 tokens/CTA.
// A (128 x 192 fp16, stride 200) in smem; B chunks (64 codes x 192)
// double-buffered via cp.async. Warp grid 4x2: wm = token group of 32,
// wn = code half of 32. Per warp m32 x n32 per chunk via m16n8k16.
// dot_acc = 256 * dot;  score = a*(Ci - dot_acc/128) + b.
// --------------------------------------------------------------------------
__device__ __forceinline__ void prefetch_b(uint32_t bbase, int c0, int tid) {
    #pragma unroll
    for (int q = 0; q < 6; q++) {
        int idx = tid + 256 * q;          // 0..1535 16B units
        int row = idx / 24, u = idx % 24;
        cp16s(bbase + row * (SA * 2) + u * 16,
              g_bcat + ((size_t)(c0 + row) * KPAD + u * 8));
    }
}

__global__ __launch_bounds__(256, 1) void argmin_mma_kernel(const float* __restrict__ x,
                                                            const float* __restrict__ emb,
                                                            const float* __restrict__ z,
                                                            float* __restrict__ out) {
    extern __shared__ __half sm[];
    // layout (halves): A[128*200] | B0[64*200] | B1[64*200] | ab(4096 f32) | Ci(128 f32)
    __half* A_s = sm;
    float*  ab  = (float*)(sm + (TOK_PB + 2 * CHUNK) * SA);
    float*  Ci_s = ab + 2 * Kc;

    __shared__ float sred_s[2][TOK_PB];
    __shared__ int   sred_i[2][TOK_PB];

    int tid  = threadIdx.x;
    int warp = tid >> 5, lane = tid & 31;
    int tok0 = blockIdx.x * TOK_PB;
    int wm = warp & 3, wn = warp >> 2;

    uint32_t smbase = smem_u32(sm);
    uint32_t b0a = smbase + TOK_PB * SA * 2;
    uint32_t b1a = b0a + CHUNK * SA * 2;

    // chunk-0 B prefetch first (overlaps A build)
    prefetch_b(b0a, 0, tid);
    cp_commit();

    // a/b tables -> smem (4096 floats, 4 x float4 per thread)
    {
        const float4* ga4 = (const float4*)g_a;
        const float4* gb4 = (const float4*)g_b;
        #pragma unroll
        for (int q = 0; q < 2; q++) ((float4*)ab)[tid + 256 * q]        = ga4[tid + 256 * q];
        #pragma unroll
        for (int q = 0; q < 2; q++) ((float4*)(ab + Kc))[tid + 256 * q] = gb4[tid + 256 * q];
    }

    // A build: one token per thread (tid<128): limbs of 16*x + Ci
    // segments: [xh, xm, xh]  (pairs with B [wh, wh, wm])
    if (tid < TOK_PB) {
        const float* xr = x + (size_t)(tok0 + tid) * Dm;
        float Ci = 0.0f;
        __half2* arow = (__half2*)(A_s + tid * SA);
        #pragma unroll
        for (int d = 0; d < Hh; d += 2) {
            float2 v = *(const float2*)(xr + d);
            Ci += v.x * v.x + v.y * v.y;
            float s0 = 16.0f * v.x, s1 = 16.0f * v.y;
            __half h0 = __float2half_rn(s0), h1 = __float2half_rn(s1);
            __half m0 = __float2half_rn(s0 - __half2float(h0));
            __half m1 = __float2half_rn(s1 - __half2float(h1));
            __half2 hh = __halves2half2(h0, h1);
            __half2 mm = __halves2half2(m0, m1);
            arow[(0 * Hh + d) >> 1] = hh;
            arow[(1 * Hh + d) >> 1] = mm;
            arow[(2 * Hh + d) >> 1] = hh;
        }
        #pragma unroll
        for (int d = 0; d < Hh; d += 4) {
            float4 v = *(const float4*)(xr + Hh + d);
            Ci += expf(v.x) + expf(v.y) + expf(v.z) + expf(v.w);
        }
        Ci_s[tid] = Ci;
    }
    __syncthreads();   // A_s, ab, Ci_s ready

    // ldmatrix per-lane offsets
    uint32_t a_off0 = smbase + ((wm * 32 + (lane & 15)) * SA + (lane >> 4) * 8) * 2;
    uint32_t a_off1 = a_off0 + 16 * SA * 2;
    uint32_t b_off = ((wn * 32 + (lane & 7) + ((lane >> 4) << 3)) * SA
                    + ((lane >> 3) & 1) * 8) * 2;

    int g  = lane >> 2, tc = lane & 3;
    float Ci_r[4];
    #pragma unroll
    for (int s = 0; s < 4; s++)
        Ci_r[s] = Ci_s[wm * 32 + (s >> 1) * 16 + (s & 1) * 8 + g];

    float best[4];
    int   bidx[4];
    #pragma unroll
    for (int s = 0; s < 4; s++) { best[s] = 3.4e38f; bidx[s] = 0; }

    for (int ch = 0; ch < NCHK; ch++) {
        uint32_t bb = (ch & 1) ? b1a : b0a;

        if (ch < NCHK - 1) {
            prefetch_b((ch & 1) ? b0a : b1a, (ch + 1) * CHUNK, tid);
            cp_commit();
            cp_wait1();           // chunk ch landed
        } else {
            cp_wait0();
        }
        __syncthreads();          // visible block-wide

        float acc[2][4][4];
        #pragma unroll
        for (int mt = 0; mt < 2; mt++)
            #pragma unroll
            for (int nt = 0; nt < 4; nt++)
                #pragma unroll
                for (int c = 0; c < 4; c++) acc[mt][nt][c] = 0.0f;

        #pragma unroll 1
        for (int k = 0; k < KIT; k++) {
            uint32_t kb = (uint32_t)k * 32;       // 16 halves
            uint32_t af0[4], af1[4], bf0[4], bf1[4];
            ldsm4(af0, a_off0 + kb);
            ldsm4(af1, a_off1 + kb);
            ldsm4(bf0, bb + b_off + kb);
            ldsm4(bf1, bb + b_off + 16 * SA * 2 + kb);
            mma16816(acc[0][0], af0, bf0 + 0);
            mma16816(acc[0][1], af0, bf0 + 2);
            mma16816(acc[0][2], af0, bf1 + 0);
            mma16816(acc[0][3], af0, bf1 + 2);
            mma16816(acc[1][0], af1, bf0 + 0);
            mma16816(acc[1][1], af1, bf0 + 2);
            mma16816(acc[1][2], af1, bf1 + 0);
            mma16816(acc[1][3], af1, bf1 + 2);
        }

        // fold scores (codes ascending; strict < keeps first min like jnp.argmin)
        int cb = ch * CHUNK + wn * 32 + 2 * tc;
        #pragma unroll
        for (int nt = 0; nt < 4; nt++) {
            int c0 = cb + nt * 8;
            float a0 = ab[c0],     b0v = ab[Kc + c0];
            float a1 = ab[c0 + 1], b1v = ab[Kc + c0 + 1];
            #pragma unroll
            for (int mt = 0; mt < 2; mt++)
                #pragma unroll
                for (int c = 0; c < 4; c++) {
                    int slot = mt * 2 + (c >> 1);
                    float aa = (c & 1) ? a1 : a0;
                    float bbv = (c & 1) ? b1v : b0v;
                    float s = fmaf(aa, fmaf(-0.0078125f, acc[mt][nt][c], Ci_r[slot]), bbv);
                    int code = c0 + (c & 1);
                    if (s < best[slot]) { best[slot] = s; bidx[slot] = code; }
                }
        }
        __syncthreads();          // all reads of bb done before it is overwritten
    }

    // reduce across the 4 tc-lanes sharing each token row
    #pragma unroll
    for (int s = 0; s < 4; s++) {
        float v = best[s];
        int   c = bidx[s];
        #pragma unroll
        for (int o = 1; o < 4; o <<= 1) {
            float v2 = __shfl_xor_sync(0xffffffffu, v, o);
            int   c2 = __shfl_xor_sync(0xffffffffu, c, o);
            if (v2 < v || (v2 == v && c2 < c)) { v = v2; c = c2; }
        }
        if (tc == 0) {
            int row = wm * 32 + (s >> 1) * 16 + (s & 1) * 8 + g;
            sred_s[wn][row] = v;
            sred_i[wn][row] = c;
        }
    }
    __syncthreads();

    if (tid < TOK_PB) {
        float s0 = sred_s[0][tid], s1 = sred_s[1][tid];
        int   c0 = sred_i[0][tid], c1 = sred_i[1][tid];
        sred_i[0][tid] = (s1 < s0 || (s1 == s0 && c1 < c0)) ? c1 : c0;
    }
    __syncthreads();

    // ---- fused epilogue: one warp per token, 16 iterations ----
    for (int it = 0; it < 16; it++) {
        int t = it * 8 + warp;
        int token = tok0 + t;
        int id = sred_i[0][t];
        const float* w  = emb + (size_t)id * Dm;
        const float* xr = x + (size_t)token * Dm;

        float4 wv = *(const float4*)(w  + lane * 4);
        float4 xv = *(const float4*)(xr + lane * 4);
        float d0 = wv.x - xv.x, d1 = wv.y - xv.y, d2 = wv.z - xv.z, d3 = wv.w - xv.w;
        float p = d0 * d0 + d1 * d1 + d2 * d2 + d3 * d3;
        #pragma unroll
        for (int o = 16; o; o >>= 1) p += __shfl_xor_sync(0xffffffffu, p, o);

        #pragma unroll
        for (int r = 0; r < 2; r++) {
            int h = lane + 32 * r;
            float mu = w[h];
            float lv = w[Hh + h];
            float zz = z[(size_t)token * Hh + h];
            out[(size_t)token * Hh + h] = fmaf(expf(0.5f * lv), zz, mu);
        }
        if (lane == 0) {
            float m = p * (1.0f / (float)Dm);
            out[OUT_IDS  + token] = (float)id;
            out[OUT_COMM + token] = m;
            out[OUT_CODE + token] = m;
        }
    }
}

// --------------------------------------------------------------------------
extern "C" void kernel_launch(void* const* d_in, const int* in_sizes, int n_in,
                              void* d_out, int out_size) {
    const float *x = nullptr, *emb = nullptr, *z = nullptr;
    for (int i = 0; i < n_in; i++) {
        if (in_sizes[i] == BT * Dm)      x   = (const float*)d_in[i];
        else if (in_sizes[i] == Kc * Dm) emb = (const float*)d_in[i];
        else if (in_sizes[i] == BT * Hh) z   = (const float*)d_in[i];
    }
    float* out = (float*)d_out;

    // dyn smem: (128 + 2*64) rows * 200 halves + ab tables + Ci
    const int SMEM_BYTES = (TOK_PB + 2 * CHUNK) * SA * 2 + 2 * Kc * 4 + TOK_PB * 4;
    cudaFuncSetAttribute(argmin_mma_kernel,
                         cudaFuncAttributeMaxDynamicSharedMemorySize, SMEM_BYTES);

    precompute_kernel<<<Kc / 8, 256>>>(emb);
    bcat_kernel<<<Kc / 4, 256>>>(emb);
    argmin_mma_kernel<<<BT / TOK_PB, 256, SMEM_BYTES>>>(x, emb, z, out);
    (void)out_size;
}